// round 2
// baseline (speedup 1.0000x reference)
#include <cuda_runtime.h>
#include <cuda_fp16.h>
#include <cstdint>
#include <cstddef>

// Problem dims
#define BATCH 512
#define ICAPS 1152
#define DDIM  8
#define JCAPS 10
#define CDIM  16

// Config
#define TPB  1024          // 32 warps; thread = (row 0..127, cpair 0..7)
#define BPC  4             // batches per CTA
#define ROWS 128           // i-rows staged per round
#define NRD  9             // 1152 / 128
#define RS   136           // smem W row stride in floats (128 + 8 pad)
#define WBUF (ROWS * RS)               // 17408 floats per W buffer
#define XBUF (BPC * ROWS * DDIM)       // 4096 floats per x buffer

// Shared layout (floats)
#define OFF_W   0
#define OFF_X   (2 * WBUF)             // 34816
#define OFF_BLP (OFF_X + 2 * XBUF)     // 43008 : b-logits [4][1152]
#define OFF_RED (OFF_BLP + BPC * ICAPS)// 47616 : S partials [32 warps][8 cp][4b*2ch]
#define OFF_RZ  (OFF_RED + 32 * 8 * 8) // 49664 : Z partials [32][4]
#define OFF_TOT (OFF_RZ + 32 * 4)      // 49792 : reduced S [4][16]
#define OFF_ZT  (OFF_TOT + 64)         // 49856 : reduced Z [4]
#define OFF_V   (OFF_ZT + 4)           // 49860 : v [4][16]
#define SMEMF   (OFF_V + 64)           // 49924 floats = 199696 B

__device__ __forceinline__ void cp16(float* dst, const float* src) {
    unsigned s = (unsigned)__cvta_generic_to_shared(dst);
    asm volatile("cp.async.cg.shared.global [%0], [%1], 16;" :: "r"(s), "l"(src));
}

__global__ void __launch_bounds__(TPB, 1)
digitcaps_kernel(const float* __restrict__ x,
                 const float* __restrict__ W,
                 float* __restrict__ out)
{
    extern __shared__ float sm[];

    const int tid  = threadIdx.x;
    const int j    = blockIdx.x % JCAPS;
    const int bg   = blockIdx.x / JCAPS;     // batch group of 4
    const int cp   = tid & 7;                // channel pair: channels 2cp, 2cp+1
    const int r    = tid >> 3;               // row-in-round 0..127
    const int lane = tid & 31;
    const int warp = tid >> 5;

    const float* Wj = W + (size_t)j * ICAPS * (DDIM * CDIM);
    const float* xg = x + (size_t)bg * BPC * ICAPS * DDIM;

    // x-staging chunk coords (1024 chunks of 16B per round: [b][row][half])
    const int xb = tid >> 8;            // batch 0..3
    const int xr = (tid >> 1) & 127;    // row
    const int xh4 = (tid & 1) * 4;      // half-row offset (floats)

    // ---- Stage round 0 (W: 4096 chunks, x: 1024 chunks) ----
    {
        float* wd = sm + OFF_W;
        #pragma unroll
        for (int k = 0; k < 4; k++) {
            int idx = k * TPB + tid;
            cp16(wd + (idx >> 5) * RS + (idx & 31) * 4, Wj + (size_t)idx * 4);
        }
        cp16(sm + OFF_X + (xb * ROWS + xr) * DDIM + xh4,
             xg + ((size_t)xb * ICAPS + xr) * DDIM + xh4);
        asm volatile("cp.async.commit_group;");
    }

    // Register-resident x_hat, fp16-packed: [batch][round] = (ch 2cp, 2cp+1)
    __half2 xh[BPC][NRD];

    // ---- Build x_hat: 9 pipelined rounds ----
    #pragma unroll
    for (int rd = 0; rd < NRD; rd++) {
        if (rd + 1 < NRD) {
            const float* wsrc = Wj + (size_t)(rd + 1) * ROWS * (DDIM * CDIM);
            float* wd = sm + OFF_W + ((rd + 1) & 1) * WBUF;
            #pragma unroll
            for (int k = 0; k < 4; k++) {
                int idx = k * TPB + tid;
                cp16(wd + (idx >> 5) * RS + (idx & 31) * 4, wsrc + (size_t)idx * 4);
            }
            cp16(sm + OFF_X + ((rd + 1) & 1) * XBUF + (xb * ROWS + xr) * DDIM + xh4,
                 xg + ((size_t)xb * ICAPS + (rd + 1) * ROWS + xr) * DDIM + xh4);
            asm volatile("cp.async.commit_group;");
            asm volatile("cp.async.wait_group 1;");
        } else {
            asm volatile("cp.async.wait_group 0;");
        }
        __syncthreads();

        const float* wrow = sm + OFF_W + (rd & 1) * WBUF + r * RS + cp * 2;
        float2 w[8];
        #pragma unroll
        for (int d = 0; d < 8; d++)
            w[d] = *reinterpret_cast<const float2*>(wrow + d * 16);

        const float* xs = sm + OFF_X + (rd & 1) * XBUF + r * DDIM;
        #pragma unroll
        for (int b = 0; b < BPC; b++) {
            float4 xa = *reinterpret_cast<const float4*>(xs + b * ROWS * DDIM);
            float4 xc = *reinterpret_cast<const float4*>(xs + b * ROWS * DDIM + 4);
            float xv[8] = {xa.x, xa.y, xa.z, xa.w, xc.x, xc.y, xc.z, xc.w};
            float s0 = 0.f, s1 = 0.f;
            #pragma unroll
            for (int d = 0; d < 8; d++) {
                s0 = fmaf(xv[d], w[d].x, s0);
                s1 = fmaf(xv[d], w[d].y, s1);
            }
            xh[b][rd] = __floats2half2_rn(s0, s1);
        }
        __syncthreads();   // protect buffer (rd&1) before restage
    }

    // ---- Routing: 3 iterations on-chip ----
    float* blp = sm + OFF_BLP;
    float* red = sm + OFF_RED;
    float* rz  = sm + OFF_RZ;
    float* tot = sm + OFF_TOT;
    float* zt  = sm + OFF_ZT;
    float* vsm = sm + OFF_V;

    #pragma unroll
    for (int it = 0; it < 3; it++) {
        float S0[BPC] = {0.f,0.f,0.f,0.f};
        float S1[BPC] = {0.f,0.f,0.f,0.f};
        float Zp[BPC];

        if (it == 0) {
            // v=0 -> uniform softmax: e=1 for every i; skip agreement entirely
            #pragma unroll
            for (int rd = 0; rd < NRD; rd++)
                #pragma unroll
                for (int b = 0; b < BPC; b++) {
                    float2 xf = __half22float2(xh[b][rd]);
                    S0[b] += xf.x;
                    S1[b] += xf.y;
                }
            #pragma unroll
            for (int b = 0; b < BPC; b++) Zp[b] = (float)NRD;
        } else {
            #pragma unroll
            for (int b = 0; b < BPC; b++) Zp[b] = 0.f;
            float2 vq[BPC];
            #pragma unroll
            for (int b = 0; b < BPC; b++)
                vq[b] = *reinterpret_cast<const float2*>(vsm + b * 16 + cp * 2);

            #pragma unroll
            for (int rd = 0; rd < NRD; rd++) {
                const int i = rd * ROWS + r;
                float  a[BPC];
                float2 xf[BPC];
                #pragma unroll
                for (int b = 0; b < BPC; b++) {
                    xf[b] = __half22float2(xh[b][rd]);
                    a[b]  = fmaf(xf[b].x, vq[b].x, xf[b].y * vq[b].y);
                }
                #pragma unroll
                for (int m = 1; m < 8; m <<= 1)
                    #pragma unroll
                    for (int b = 0; b < BPC; b++)
                        a[b] += __shfl_xor_sync(0xffffffffu, a[b], m);

                #pragma unroll
                for (int b = 0; b < BPC; b++) {
                    float nb = a[b];
                    if (it == 2) {
                        nb += blp[b * ICAPS + i];       // logits stored in iter 1
                    } else if (cp == 0) {
                        blp[b * ICAPS + i] = nb;        // iter 1: b was 0 before
                    }
                    float e = __expf(nb);
                    Zp[b] += e;
                    S0[b] = fmaf(e, xf[b].x, S0[b]);
                    S1[b] = fmaf(e, xf[b].y, S1[b]);
                }
            }
        }

        // Reduce over same-cp lanes within warp (r sub-rows: masks 8,16)
        #pragma unroll
        for (int m = 8; m < 32; m <<= 1)
            #pragma unroll
            for (int b = 0; b < BPC; b++) {
                S0[b] += __shfl_xor_sync(0xffffffffu, S0[b], m);
                S1[b] += __shfl_xor_sync(0xffffffffu, S1[b], m);
                Zp[b] += __shfl_xor_sync(0xffffffffu, Zp[b], m);
            }
        if (lane < 8) {   // lane == cp
            #pragma unroll
            for (int b = 0; b < BPC; b++) {
                red[(warp * 8 + cp) * 8 + b * 2 + 0] = S0[b];
                red[(warp * 8 + cp) * 8 + b * 2 + 1] = S1[b];
            }
        }
        if (lane == 0) {
            #pragma unroll
            for (int b = 0; b < BPC; b++) rz[warp * 4 + b] = Zp[b];
        }
        __syncthreads();

        // Cross-warp reduction
        if (tid < 64) {
            const int b = tid >> 4, c = tid & 15;
            float s = 0.f;
            #pragma unroll
            for (int w2 = 0; w2 < 32; w2++)
                s += red[(w2 * 8 + (c >> 1)) * 8 + b * 2 + (c & 1)];
            tot[b * 16 + c] = s;
        } else if (tid < 68) {
            const int b = tid - 64;
            float s = 0.f;
            #pragma unroll
            for (int w2 = 0; w2 < 32; w2++) s += rz[w2 * 4 + b];
            zt[b] = s;
        }
        __syncthreads();

        // squash: one thread per batch
        if (tid < BPC) {
            const int b = tid;
            float inv = 1.f / zt[b];
            float sv[16], n2 = 0.f;
            #pragma unroll
            for (int c = 0; c < 16; c++) {
                sv[c] = tot[b * 16 + c] * inv;
                n2 += sv[c] * sv[c];
            }
            float nr = sqrtf(n2);
            float coef = (n2 / (1.f + n2)) / (nr + 1e-7f);
            #pragma unroll
            for (int c = 0; c < 16; c++) vsm[b * 16 + c] = coef * sv[c];
        }
        __syncthreads();
    }

    // ---- Output: (B, J, C) ----
    if (tid < 64) {
        const int b = tid >> 4, c = tid & 15;
        out[((size_t)(bg * BPC + b) * JCAPS + j) * CDIM + c] = vsm[b * 16 + c];
    }
}

extern "C" void kernel_launch(void* const* d_in, const int* in_sizes, int n_in,
                              void* d_out, int out_size)
{
    const float* x = (const float*)d_in[0];
    const float* W = (const float*)d_in[1];
    if (n_in >= 2 &&
        in_sizes[0] == JCAPS * ICAPS * DDIM * CDIM &&
        in_sizes[1] == BATCH * ICAPS * DDIM) {
        const float* t = x; x = W; W = t;
    }
    float* out = (float*)d_out;

    cudaFuncSetAttribute(digitcaps_kernel,
                         cudaFuncAttributeMaxDynamicSharedMemorySize,
                         SMEMF * (int)sizeof(float));

    dim3 grid((BATCH / BPC) * JCAPS);   // 1280 CTAs: one per (j, batch-quad)
    digitcaps_kernel<<<grid, TPB, SMEMF * sizeof(float)>>>(x, W, out);
}

// round 3
// speedup vs baseline: 1.0577x; 1.0577x over previous
#include <cuda_runtime.h>
#include <cuda_fp16.h>
#include <cstdint>
#include <cstddef>

// Problem dims
#define BATCH 512
#define ICAPS 1152
#define DDIM  8
#define JCAPS 10
#define CDIM  16

// Config: thread = (r = i-row 0..127, b = batch 0..3)
#define TPB  512
#define BPC  4
#define ROWS 128
#define NRD  9             // 1152 / 128
#define WRS  132           // W smem row stride (128 + 4 pad): 132 mod 32 = 4 -> 8 rows/warp bank-disjoint
#define WBUF (ROWS * WRS)  // 16896 floats
#define XRS  12            // x smem row stride (8 + 4 pad): lane*12 mod 32 -> conflict-free 4-phase LDS.128
#define XBUF (TPB * XRS)   // 6144 floats

// Shared layout (floats)
#define OFF_W   0
#define OFF_X   (2 * WBUF)              // 33792
#define OFF_RED (OFF_X + 2 * XBUF)      // 46080 : [16 warps][4 b][17]
#define OFF_TOT (OFF_RED + 16 * 4 * 17) // 47168 : S totals [4][16]
#define OFF_ZT  (OFF_TOT + 64)          // 47232 : Z totals [4]
#define OFF_V   (OFF_ZT + 4)            // 47236 : v [4][16]
#define SMEMF   (OFF_V + 64)            // 47300 floats = 189200 B

__device__ __forceinline__ void cp16(float* dst, const float* src) {
    unsigned s = (unsigned)__cvta_generic_to_shared(dst);
    asm volatile("cp.async.cg.shared.global [%0], [%1], 16;" :: "r"(s), "l"(src));
}

__global__ void __launch_bounds__(TPB, 1)
digitcaps_kernel(const float* __restrict__ x,
                 const float* __restrict__ W,
                 float* __restrict__ out)
{
    extern __shared__ float sm[];

    const int tid  = threadIdx.x;
    const int j    = blockIdx.x % JCAPS;
    const int bg   = blockIdx.x / JCAPS;     // batch group of 4
    const int b4   = tid & 3;                // batch within group
    const int r    = tid >> 2;               // i-row within round
    const int lane = tid & 31;
    const int warp = tid >> 5;

    const float* Wj = W + (size_t)j * ICAPS * (DDIM * CDIM);
    const float* xg = x + (size_t)bg * BPC * ICAPS * DDIM;

    // x staging coords: 1024 16B-chunks/round -> 2 per thread
    // chunk c: b' = c>>8, i_loc = (c>>1)&127, half = c&1 ; dst row = i_loc*4+b'
    // W staging: 4096 chunks/round -> 8 per thread

    // ---- Stage round 0 ----
    {
        #pragma unroll
        for (int k = 0; k < 8; k++) {
            int idx = k * TPB + tid;
            cp16(sm + OFF_W + (idx >> 5) * WRS + (idx & 31) * 4, Wj + (size_t)idx * 4);
        }
        #pragma unroll
        for (int k = 0; k < 2; k++) {
            int c = k * TPB + tid;
            int bb = c >> 8, il = (c >> 1) & 127, hf = c & 1;
            cp16(sm + OFF_X + ((il << 2) + bb) * XRS + hf * 4,
                 xg + ((size_t)bb * ICAPS + il) * DDIM + hf * 4);
        }
        asm volatile("cp.async.commit_group;");
    }

    // Register-resident x_hat (fp16 storage, fp32 math): [round][8 half2]
    __half2 xh[NRD][8];

    // ---- Build: 9 pipelined rounds ----
    #pragma unroll
    for (int rd = 0; rd < NRD; rd++) {
        if (rd + 1 < NRD) {
            const float* wsrc = Wj + (size_t)(rd + 1) * ROWS * (DDIM * CDIM);
            float* wd = sm + OFF_W + ((rd + 1) & 1) * WBUF;
            #pragma unroll
            for (int k = 0; k < 8; k++) {
                int idx = k * TPB + tid;
                cp16(wd + (idx >> 5) * WRS + (idx & 31) * 4, wsrc + (size_t)idx * 4);
            }
            float* xd = sm + OFF_X + ((rd + 1) & 1) * XBUF;
            #pragma unroll
            for (int k = 0; k < 2; k++) {
                int c = k * TPB + tid;
                int bb = c >> 8, il = (c >> 1) & 127, hf = c & 1;
                cp16(xd + ((il << 2) + bb) * XRS + hf * 4,
                     xg + ((size_t)bb * ICAPS + (rd + 1) * ROWS + il) * DDIM + hf * 4);
            }
            asm volatile("cp.async.commit_group;");
            asm volatile("cp.async.wait_group 1;");
        } else {
            asm volatile("cp.async.wait_group 0;");
        }
        __syncthreads();

        const int buf = rd & 1;
        const float* xp = sm + OFF_X + buf * XBUF + tid * XRS;
        float4 x_a = *reinterpret_cast<const float4*>(xp);
        float4 x_b = *reinterpret_cast<const float4*>(xp + 4);
        float xv[8] = {x_a.x, x_a.y, x_a.z, x_a.w, x_b.x, x_b.y, x_b.z, x_b.w};

        const float* wrow = sm + OFF_W + buf * WBUF + r * WRS;
        float acc[16];
        #pragma unroll
        for (int c = 0; c < 16; c++) acc[c] = 0.f;

        #pragma unroll
        for (int d = 0; d < 8; d++) {
            const float4* wd4 = reinterpret_cast<const float4*>(wrow + d * 16);
            float4 w0 = wd4[0], w1 = wd4[1], w2 = wd4[2], w3 = wd4[3];
            float xs = xv[d];
            acc[0]  = fmaf(xs, w0.x, acc[0]);
            acc[1]  = fmaf(xs, w0.y, acc[1]);
            acc[2]  = fmaf(xs, w0.z, acc[2]);
            acc[3]  = fmaf(xs, w0.w, acc[3]);
            acc[4]  = fmaf(xs, w1.x, acc[4]);
            acc[5]  = fmaf(xs, w1.y, acc[5]);
            acc[6]  = fmaf(xs, w1.z, acc[6]);
            acc[7]  = fmaf(xs, w1.w, acc[7]);
            acc[8]  = fmaf(xs, w2.x, acc[8]);
            acc[9]  = fmaf(xs, w2.y, acc[9]);
            acc[10] = fmaf(xs, w2.z, acc[10]);
            acc[11] = fmaf(xs, w2.w, acc[11]);
            acc[12] = fmaf(xs, w3.x, acc[12]);
            acc[13] = fmaf(xs, w3.y, acc[13]);
            acc[14] = fmaf(xs, w3.z, acc[14]);
            acc[15] = fmaf(xs, w3.w, acc[15]);
        }
        #pragma unroll
        for (int k = 0; k < 8; k++)
            xh[rd][k] = __floats2half2_rn(acc[2 * k], acc[2 * k + 1]);

        __syncthreads();   // protect buffer before restage
    }

    // ---- Routing: 3 iterations; logits thread-local ----
    float* red = sm + OFF_RED;
    float* tot = sm + OFF_TOT;
    float* zt  = sm + OFF_ZT;
    float* vsm = sm + OFF_V;

    float lg[NRD];   // accumulated routing logits for this thread's (b, i) rows

    #pragma unroll
    for (int it = 0; it < 3; it++) {
        float S[16];
        #pragma unroll
        for (int c = 0; c < 16; c++) S[c] = 0.f;
        float Z;

        if (it == 0) {
            // b = 0 -> uniform weights: skip softmax entirely
            #pragma unroll
            for (int rd = 0; rd < NRD; rd++)
                #pragma unroll
                for (int k = 0; k < 8; k++) {
                    float2 f = __half22float2(xh[rd][k]);
                    S[2 * k]     += f.x;
                    S[2 * k + 1] += f.y;
                }
            Z = (float)NRD;
        } else {
            Z = 0.f;
            float vv[16];
            {
                const float4* vp = reinterpret_cast<const float4*>(vsm + b4 * 16);
                float4 v0 = vp[0], v1 = vp[1], v2 = vp[2], v3 = vp[3];
                vv[0]=v0.x; vv[1]=v0.y; vv[2]=v0.z; vv[3]=v0.w;
                vv[4]=v1.x; vv[5]=v1.y; vv[6]=v1.z; vv[7]=v1.w;
                vv[8]=v2.x; vv[9]=v2.y; vv[10]=v2.z; vv[11]=v2.w;
                vv[12]=v3.x; vv[13]=v3.y; vv[14]=v3.z; vv[15]=v3.w;
            }
            #pragma unroll
            for (int rd = 0; rd < NRD; rd++) {
                // agreement: thread-local dot, no shuffles
                float a = 0.f;
                #pragma unroll
                for (int k = 0; k < 8; k++) {
                    float2 f = __half22float2(xh[rd][k]);
                    a = fmaf(vv[2 * k], f.x, a);
                    a = fmaf(vv[2 * k + 1], f.y, a);
                }
                float nb;
                if (it == 1) { nb = a; lg[rd] = nb; }
                else         { nb = lg[rd] + a; }
                float e = __expf(nb);   // |nb| small: un-normalized softmax is exact
                Z += e;
                #pragma unroll
                for (int k = 0; k < 8; k++) {
                    float2 f = __half22float2(xh[rd][k]);
                    S[2 * k]     = fmaf(e, f.x, S[2 * k]);
                    S[2 * k + 1] = fmaf(e, f.y, S[2 * k + 1]);
                }
            }
        }

        // Reduce over the 8 r-rows within each warp (b4 bits preserved)
        #pragma unroll
        for (int m = 4; m < 32; m <<= 1) {
            #pragma unroll
            for (int c = 0; c < 16; c++)
                S[c] += __shfl_xor_sync(0xffffffffu, S[c], m);
            Z += __shfl_xor_sync(0xffffffffu, Z, m);
        }
        // Every lane now holds the warp-total for its b4; lanes store cooperatively
        {
            const int cidx = lane >> 2;   // 0..7
            float* rp = red + (warp * 4 + b4) * 17;
            rp[cidx]     = S[cidx];
            rp[cidx + 8] = S[cidx + 8];
            if (lane < 4) red[(warp * 4 + lane) * 17 + 16] = Z;  // lane == b4 here
        }
        __syncthreads();

        // Cross-warp reduction
        if (tid < 64) {
            const int bb = tid & 3, c = tid >> 2;
            float s = 0.f;
            #pragma unroll
            for (int w2 = 0; w2 < 16; w2++)
                s += red[(w2 * 4 + bb) * 17 + c];
            tot[bb * 16 + c] = s;
        } else if (tid < 68) {
            const int bb = tid - 64;
            float z = 0.f;
            #pragma unroll
            for (int w2 = 0; w2 < 16; w2++)
                z += red[(w2 * 4 + bb) * 17 + 16];
            zt[bb] = z;
        }
        __syncthreads();

        // squash per batch
        if (tid < BPC) {
            const int bb = tid;
            float inv = 1.f / zt[bb];
            float sv[16], n2 = 0.f;
            #pragma unroll
            for (int c = 0; c < 16; c++) {
                sv[c] = tot[bb * 16 + c] * inv;
                n2 += sv[c] * sv[c];
            }
            float nr = sqrtf(n2);
            float coef = (n2 / (1.f + n2)) / (nr + 1e-7f);
            #pragma unroll
            for (int c = 0; c < 16; c++) vsm[bb * 16 + c] = coef * sv[c];
        }
        __syncthreads();
    }

    // ---- Output (B, J, C) ----
    if (tid < 64) {
        const int bb = tid >> 4, c = tid & 15;
        out[((size_t)(bg * BPC + bb) * JCAPS + j) * CDIM + c] = vsm[bb * 16 + c];
    }
}

extern "C" void kernel_launch(void* const* d_in, const int* in_sizes, int n_in,
                              void* d_out, int out_size)
{
    const float* x = (const float*)d_in[0];
    const float* W = (const float*)d_in[1];
    if (n_in >= 2 &&
        in_sizes[0] == JCAPS * ICAPS * DDIM * CDIM &&
        in_sizes[1] == BATCH * ICAPS * DDIM) {
        const float* t = x; x = W; W = t;
    }
    float* out = (float*)d_out;

    cudaFuncSetAttribute(digitcaps_kernel,
                         cudaFuncAttributeMaxDynamicSharedMemorySize,
                         SMEMF * (int)sizeof(float));

    dim3 grid((BATCH / BPC) * JCAPS);   // 1280 CTAs
    digitcaps_kernel<<<grid, TPB, SMEMF * sizeof(float)>>>(x, W, out);
}

// round 4
// speedup vs baseline: 1.1113x; 1.0507x over previous
#include <cuda_runtime.h>
#include <cuda_fp16.h>
#include <cstdint>
#include <cstddef>

// Problem dims
#define BATCH 512
#define ICAPS 1152
#define DDIM  8
#define JCAPS 10
#define CDIM  16

// Config: thread = (r = i-row 0..127, b = batch 0..3)
#define TPB  512
#define BPC  4
#define ROWS 128
#define NRD  9
#define WRS  132           // W smem row stride in floats (128+4 pad)
#define WBUF (ROWS * WRS)  // 16896 floats
#define XRS  12            // x smem row stride (8+4 pad)
#define XBUF (TPB * XRS)   // 6144 floats

// Shared layout (floats)
#define OFF_W   0
#define OFF_X   (2 * WBUF)              // 33792
#define OFF_RED (OFF_X + 2 * XBUF)      // 46080 : [16 warps][4 b][17]
#define OFF_TOT (OFF_RED + 16 * 4 * 17) // 47168
#define OFF_ZT  (OFF_TOT + 64)          // 47232
#define OFF_V   (OFF_ZT + 4)            // 47236
#define SMEMF   (OFF_V + 64)            // 47300 floats = 189200 B

typedef unsigned long long u64;

__device__ __forceinline__ void cp16(float* dst, const float* src) {
    unsigned s = (unsigned)__cvta_generic_to_shared(dst);
    asm volatile("cp.async.cg.shared.global [%0], [%1], 16;" :: "r"(s), "l"(src));
}
__device__ __forceinline__ u64 pack2(float lo, float hi) {
    u64 r; asm("mov.b64 %0, {%1, %2};" : "=l"(r) : "f"(lo), "f"(hi)); return r;
}
__device__ __forceinline__ void unpack2(u64 v, float& lo, float& hi) {
    asm("mov.b64 {%0, %1}, %2;" : "=f"(lo), "=f"(hi) : "l"(v));
}
__device__ __forceinline__ void ffma2(u64& d, u64 a, u64 b) {
    asm("fma.rn.f32x2 %0, %1, %2, %0;" : "+l"(d) : "l"(a), "l"(b));
}
__device__ __forceinline__ void fadd2(u64& d, u64 a) {
    asm("add.rn.f32x2 %0, %0, %1;" : "+l"(d) : "l"(a));
}

__global__ void __launch_bounds__(TPB, 1)
digitcaps_kernel(const float* __restrict__ x,
                 const float* __restrict__ W,
                 float* __restrict__ out)
{
    extern __shared__ float sm[];

    const int tid  = threadIdx.x;
    const int j    = blockIdx.x % JCAPS;
    const int bg   = blockIdx.x / JCAPS;
    const int b4   = tid & 3;
    const int r    = tid >> 2;
    const int lane = tid & 31;
    const int warp = tid >> 5;

    const float* Wj = W + (size_t)j * ICAPS * (DDIM * CDIM);
    const float* xg = x + (size_t)bg * BPC * ICAPS * DDIM;

    // x staging coords
    const int xc0 = tid, xc1 = TPB + tid;
    const int bb0 = xc0 >> 8, il0 = (xc0 >> 1) & 127, hf0 = (xc0 & 1) * 4;
    const int bb1 = xc1 >> 8, il1 = (xc1 >> 1) & 127, hf1 = (xc1 & 1) * 4;

    // ---- Prologue: stage round 0 ----
    {
        #pragma unroll
        for (int k = 0; k < 8; k++) {
            int idx = k * TPB + tid;
            cp16(sm + OFF_W + (idx >> 5) * WRS + (idx & 31) * 4, Wj + (size_t)idx * 4);
        }
        cp16(sm + OFF_X + ((il0 << 2) + bb0) * XRS + hf0, xg + ((size_t)bb0 * ICAPS + il0) * DDIM + hf0);
        cp16(sm + OFF_X + ((il1 << 2) + bb1) * XRS + hf1, xg + ((size_t)bb1 * ICAPS + il1) * DDIM + hf1);
        asm volatile("cp.async.commit_group;");
    }

    __half2 xh[NRD][8];       // fp16-packed x_hat
    u64 S0p[8];               // iter-0 S accumulated in fp32 during build
    #pragma unroll
    for (int k = 0; k < 8; k++) S0p[k] = 0ull;

    // ---- Build: 9 rounds, ONE sync per round ----
    #pragma unroll
    for (int rd = 0; rd < NRD; rd++) {
        asm volatile("cp.async.wait_group 0;");
        __syncthreads();                       // data rd visible; all warps done with rd-1

        if (rd + 1 < NRD) {                    // stage rd+1 into the buffer last read in rd-1
            const float* wsrc = Wj + (size_t)(rd + 1) * ROWS * (DDIM * CDIM);
            float* wd = sm + OFF_W + ((rd + 1) & 1) * WBUF;
            #pragma unroll
            for (int k = 0; k < 8; k++) {
                int idx = k * TPB + tid;
                cp16(wd + (idx >> 5) * WRS + (idx & 31) * 4, wsrc + (size_t)idx * 4);
            }
            float* xd = sm + OFF_X + ((rd + 1) & 1) * XBUF;
            cp16(xd + ((il0 << 2) + bb0) * XRS + hf0,
                 xg + ((size_t)bb0 * ICAPS + (rd + 1) * ROWS + il0) * DDIM + hf0);
            cp16(xd + ((il1 << 2) + bb1) * XRS + hf1,
                 xg + ((size_t)bb1 * ICAPS + (rd + 1) * ROWS + il1) * DDIM + hf1);
            asm volatile("cp.async.commit_group;");
        }

        const int buf = rd & 1;
        const float* xp = sm + OFF_X + buf * XBUF + tid * XRS;
        float4 x_a = *reinterpret_cast<const float4*>(xp);
        float4 x_b = *reinterpret_cast<const float4*>(xp + 4);
        float xv[8] = {x_a.x, x_a.y, x_a.z, x_a.w, x_b.x, x_b.y, x_b.z, x_b.w};

        const ulonglong2* wp =
            reinterpret_cast<const ulonglong2*>(sm + OFF_W + buf * WBUF + r * WRS);

        u64 acc2[8];
        #pragma unroll
        for (int k = 0; k < 8; k++) acc2[k] = 0ull;

        #pragma unroll
        for (int d = 0; d < 8; d++) {           // 64 FFMA2 = 128 FMA
            ulonglong2 w0 = wp[d * 4 + 0];
            ulonglong2 w1 = wp[d * 4 + 1];
            ulonglong2 w2 = wp[d * 4 + 2];
            ulonglong2 w3 = wp[d * 4 + 3];
            u64 xs2 = pack2(xv[d], xv[d]);
            ffma2(acc2[0], xs2, w0.x);  ffma2(acc2[1], xs2, w0.y);
            ffma2(acc2[2], xs2, w1.x);  ffma2(acc2[3], xs2, w1.y);
            ffma2(acc2[4], xs2, w2.x);  ffma2(acc2[5], xs2, w2.y);
            ffma2(acc2[6], xs2, w3.x);  ffma2(acc2[7], xs2, w3.y);
        }
        #pragma unroll
        for (int k = 0; k < 8; k++) {
            float lo, hi; unpack2(acc2[k], lo, hi);
            xh[rd][k] = __floats2half2_rn(lo, hi);
            fadd2(S0p[k], acc2[k]);             // fold iter-0 sum (exact fp32)
        }
        // no trailing sync: next round's sync protects the buffers
    }

    // ---- Routing ----
    float* red = sm + OFF_RED;
    float* tot = sm + OFF_TOT;
    float* zt  = sm + OFF_ZT;
    float* vsm = sm + OFF_V;
    float lg[NRD];

    #pragma unroll
    for (int it = 0; it < 3; it++) {
        float S[16];
        float Zp;

        if (it == 0) {
            #pragma unroll
            for (int k = 0; k < 8; k++) unpack2(S0p[k], S[2 * k], S[2 * k + 1]);
            Zp = (float)NRD;                     // uniform weights, exp(0)=1
        } else {
            u64 Sp2[8];
            #pragma unroll
            for (int k = 0; k < 8; k++) Sp2[k] = 0ull;
            Zp = 0.f;

            #pragma unroll
            for (int rd = 0; rd < NRD; rd++) {
                u64 a2 = 0ull;
                u64 xf2[8];
                #pragma unroll
                for (int k = 0; k < 8; k++) {
                    float lo = __low2float(xh[rd][k]);
                    float hi = __high2float(xh[rd][k]);
                    xf2[k] = pack2(lo, hi);
                    u64 v2 = pack2(vsm[b4 * 16 + 2 * k], vsm[b4 * 16 + 2 * k + 1]);
                    ffma2(a2, v2, xf2[k]);       // agreement dot, pairwise
                }
                float alo, ahi; unpack2(a2, alo, ahi);
                float a = alo + ahi;
                float nb;
                if (it == 1) { nb = a; lg[rd] = nb; }
                else         { nb = lg[rd] + a; }
                float e = __expf(nb);
                Zp += e;
                u64 e2 = pack2(e, e);
                #pragma unroll
                for (int k = 0; k < 8; k++)
                    ffma2(Sp2[k], e2, xf2[k]);   // S += e * x_hat
            }
            #pragma unroll
            for (int k = 0; k < 8; k++) unpack2(Sp2[k], S[2 * k], S[2 * k + 1]);
        }

        // warp reduce over the 8 same-b4 lanes
        #pragma unroll
        for (int m = 4; m < 32; m <<= 1) {
            #pragma unroll
            for (int c = 0; c < 16; c++)
                S[c] += __shfl_xor_sync(0xffffffffu, S[c], m);
            Zp += __shfl_xor_sync(0xffffffffu, Zp, m);
        }
        {
            const int cidx = lane >> 2;
            float* rp = red + (warp * 4 + b4) * 17;
            rp[cidx]     = S[cidx];
            rp[cidx + 8] = S[cidx + 8];
            if (lane < 4) red[(warp * 4 + lane) * 17 + 16] = Zp;
        }
        __syncthreads();

        if (tid < 64) {
            const int bb = tid & 3, c = tid >> 2;
            float s = 0.f;
            #pragma unroll
            for (int w2 = 0; w2 < 16; w2++)
                s += red[(w2 * 4 + bb) * 17 + c];
            tot[bb * 16 + c] = s;
        } else if (tid < 68) {
            const int bb = tid - 64;
            float z = 0.f;
            #pragma unroll
            for (int w2 = 0; w2 < 16; w2++)
                z += red[(w2 * 4 + bb) * 17 + 16];
            zt[bb] = z;
        }
        __syncthreads();

        if (tid < BPC) {
            const int bb = tid;
            float inv = 1.f / zt[bb];
            float sv[16], n2 = 0.f;
            #pragma unroll
            for (int c = 0; c < 16; c++) {
                sv[c] = tot[bb * 16 + c] * inv;
                n2 += sv[c] * sv[c];
            }
            float nr = sqrtf(n2);
            float coef = (n2 / (1.f + n2)) / (nr + 1e-7f);
            #pragma unroll
            for (int c = 0; c < 16; c++) vsm[bb * 16 + c] = coef * sv[c];
        }
        __syncthreads();
    }

    // ---- Output (B, J, C) ----
    if (tid < 64) {
        const int bb = tid >> 4, c = tid & 15;
        out[((size_t)(bg * BPC + bb) * JCAPS + j) * CDIM + c] = vsm[bb * 16 + c];
    }
}

extern "C" void kernel_launch(void* const* d_in, const int* in_sizes, int n_in,
                              void* d_out, int out_size)
{
    const float* x = (const float*)d_in[0];
    const float* W = (const float*)d_in[1];
    if (n_in >= 2 &&
        in_sizes[0] == JCAPS * ICAPS * DDIM * CDIM &&
        in_sizes[1] == BATCH * ICAPS * DDIM) {
        const float* t = x; x = W; W = t;
    }
    float* out = (float*)d_out;

    cudaFuncSetAttribute(digitcaps_kernel,
                         cudaFuncAttributeMaxDynamicSharedMemorySize,
                         SMEMF * (int)sizeof(float));

    dim3 grid((BATCH / BPC) * JCAPS);
    digitcaps_kernel<<<grid, TPB, SMEMF * sizeof(float)>>>(x, W, out);
}

// round 5
// speedup vs baseline: 1.2937x; 1.1641x over previous
#include <cuda_runtime.h>
#include <cuda_fp16.h>
#include <cstdint>
#include <cstddef>

// Problem dims
#define BATCH 512
#define ICAPS 1152
#define DDIM  8
#define JCAPS 10
#define CDIM  16

// Config: thread = (r = i-row 0..127, b4 = batch 0..3)
#define TPB  512
#define BPC  4
#define ROWS 128
#define NRD  9
#define WRS  132                 // W smem row stride (128+4): LDS.128 phases conflict-free
#define WSZ  (ROWS * WRS)        // 16896 floats (single buffer)

// Shared layout (float/u32 units)
#define OFF_W   0
#define OFF_XH  WSZ                       // x_hat: 1152*4 rows x 8 u32 (half2), XOR-swizzled
#define XH_U32  (ICAPS * BPC * 8)         // 36864
#define OFF_RED (OFF_XH + XH_U32)         // 53760 : [16 warps][4 b][17]
#define OFF_TOT (OFF_RED + 16 * 4 * 17)   // 54848
#define OFF_ZT  (OFF_TOT + 64)            // 54912
#define OFF_V   (OFF_ZT + 4)              // 54916
#define SMEMF   (OFF_V + 64)              // 54980 floats = 219920 B

__device__ __forceinline__ void cp16(float* dst, const float* src) {
    unsigned s = (unsigned)__cvta_generic_to_shared(dst);
    asm volatile("cp.async.cg.shared.global [%0], [%1], 16;" :: "r"(s), "l"(src));
}

__global__ void __launch_bounds__(TPB, 1)
digitcaps_kernel(const float* __restrict__ x,
                 const float* __restrict__ W,
                 float* __restrict__ out)
{
    extern __shared__ float sm[];

    const int tid  = threadIdx.x;
    const int j    = blockIdx.x % JCAPS;
    const int bg   = blockIdx.x / JCAPS;
    const int b4   = tid & 3;
    const int r    = tid >> 2;
    const int r7   = r & 7;
    const int lane = tid & 31;
    const int warp = tid >> 5;

    const float* Wj = W + (size_t)j * ICAPS * (DDIM * CDIM);
    const float* xg = x + ((size_t)bg * BPC + b4) * ICAPS * DDIM;

    unsigned* xhb = reinterpret_cast<unsigned*>(sm + OFF_XH);

    // ---- Prologue: stage W round 0, prefetch x round 0 ----
    #pragma unroll
    for (int k = 0; k < 8; k++) {
        int idx = k * TPB + tid;
        cp16(sm + OFF_W + (idx >> 5) * WRS + (idx & 31) * 4, Wj + (size_t)idx * 4);
    }
    asm volatile("cp.async.commit_group;");

    float4 xa = *reinterpret_cast<const float4*>(xg + (size_t)r * DDIM);
    float4 xb = *reinterpret_cast<const float4*>(xg + (size_t)r * DDIM + 4);

    float S0[16];
    #pragma unroll
    for (int c = 0; c < 16; c++) S0[c] = 0.f;

    // ---- Build: 9 rounds, single W buffer, zero register spills ----
    #pragma unroll
    for (int rd = 0; rd < NRD; rd++) {
        asm volatile("cp.async.wait_group 0;");
        __syncthreads();                       // W[rd] visible to all

        float xv[8] = {xa.x, xa.y, xa.z, xa.w, xb.x, xb.y, xb.z, xb.w};
        if (rd + 1 < NRD) {                    // prefetch next x (global, L2-resident)
            const float* xp = xg + (size_t)((rd + 1) * ROWS + r) * DDIM;
            xa = *reinterpret_cast<const float4*>(xp);
            xb = *reinterpret_cast<const float4*>(xp + 4);
        }

        const float* wrow = sm + OFF_W + r * WRS;
        float acc[16];
        #pragma unroll
        for (int c = 0; c < 16; c++) acc[c] = 0.f;

        #pragma unroll
        for (int d = 0; d < 8; d++) {
            const float4* wd4 = reinterpret_cast<const float4*>(wrow + d * 16);
            float4 w0 = wd4[0], w1 = wd4[1], w2 = wd4[2], w3 = wd4[3];
            float xs = xv[d];
            acc[0]  = fmaf(xs, w0.x, acc[0]);
            acc[1]  = fmaf(xs, w0.y, acc[1]);
            acc[2]  = fmaf(xs, w0.z, acc[2]);
            acc[3]  = fmaf(xs, w0.w, acc[3]);
            acc[4]  = fmaf(xs, w1.x, acc[4]);
            acc[5]  = fmaf(xs, w1.y, acc[5]);
            acc[6]  = fmaf(xs, w1.z, acc[6]);
            acc[7]  = fmaf(xs, w1.w, acc[7]);
            acc[8]  = fmaf(xs, w2.x, acc[8]);
            acc[9]  = fmaf(xs, w2.y, acc[9]);
            acc[10] = fmaf(xs, w2.z, acc[10]);
            acc[11] = fmaf(xs, w2.w, acc[11]);
            acc[12] = fmaf(xs, w3.x, acc[12]);
            acc[13] = fmaf(xs, w3.y, acc[13]);
            acc[14] = fmaf(xs, w3.z, acc[14]);
            acc[15] = fmaf(xs, w3.w, acc[15]);
        }

        // Store x_hat (fp16, XOR-swizzled: word k at k^r7) + fold iter-0 sum
        unsigned* xrow = xhb + (size_t)(((rd * ROWS + r) << 2) + b4) * 8;
        #pragma unroll
        for (int k = 0; k < 8; k++) {
            __half2 h = __floats2half2_rn(acc[2 * k], acc[2 * k + 1]);
            xrow[k ^ r7] = *reinterpret_cast<unsigned*>(&h);
            S0[2 * k]     += acc[2 * k];
            S0[2 * k + 1] += acc[2 * k + 1];
        }

        __syncthreads();                       // all done reading W[rd]
        if (rd + 1 < NRD) {
            const float* wsrc = Wj + (size_t)(rd + 1) * ROWS * (DDIM * CDIM);
            #pragma unroll
            for (int k = 0; k < 8; k++) {
                int idx = k * TPB + tid;
                cp16(sm + OFF_W + (idx >> 5) * WRS + (idx & 31) * 4, wsrc + (size_t)idx * 4);
            }
            asm volatile("cp.async.commit_group;");
        }
    }

    // ---- Routing: 3 iterations; x_hat streamed from smem (own rows only) ----
    float* red = sm + OFF_RED;
    float* tot = sm + OFF_TOT;
    float* zt  = sm + OFF_ZT;
    float* vsm = sm + OFF_V;
    float lg[NRD];

    #pragma unroll
    for (int it = 0; it < 3; it++) {
        float S[16];
        float Zp;

        if (it == 0) {
            #pragma unroll
            for (int c = 0; c < 16; c++) S[c] = S0[c];
            Zp = (float)NRD;                   // uniform softmax (b=0)
        } else {
            #pragma unroll
            for (int c = 0; c < 16; c++) S[c] = 0.f;
            Zp = 0.f;
            float vv[16];
            #pragma unroll
            for (int c = 0; c < 16; c++) vv[c] = vsm[b4 * 16 + c];

            #pragma unroll
            for (int rd = 0; rd < NRD; rd++) {
                const unsigned* xrow = xhb + (size_t)(((rd * ROWS + r) << 2) + b4) * 8;
                float xf[16];
                #pragma unroll
                for (int k = 0; k < 8; k++) {
                    unsigned u = xrow[k ^ r7];
                    __half2 h = *reinterpret_cast<__half2*>(&u);
                    float2 f = __half22float2(h);
                    xf[2 * k] = f.x; xf[2 * k + 1] = f.y;
                }
                float a = 0.f;
                #pragma unroll
                for (int c = 0; c < 16; c++) a = fmaf(vv[c], xf[c], a);
                float nb;
                if (it == 1) { nb = a; lg[rd] = nb; }
                else         { nb = lg[rd] + a; }
                float e = __expf(nb);          // |nb| small: un-normalized softmax exact
                Zp += e;
                #pragma unroll
                for (int c = 0; c < 16; c++) S[c] = fmaf(e, xf[c], S[c]);
            }
        }

        // Warp reduce over the 8 same-b4 lanes
        #pragma unroll
        for (int m = 4; m < 32; m <<= 1) {
            #pragma unroll
            for (int c = 0; c < 16; c++)
                S[c] += __shfl_xor_sync(0xffffffffu, S[c], m);
            Zp += __shfl_xor_sync(0xffffffffu, Zp, m);
        }
        {
            const int cidx = lane >> 2;
            float* rp = red + (warp * 4 + b4) * 17;
            rp[cidx]     = S[cidx];
            rp[cidx + 8] = S[cidx + 8];
            if (lane < 4) red[(warp * 4 + lane) * 17 + 16] = Zp;
        }
        __syncthreads();

        if (tid < 64) {
            const int bb = tid & 3, c = tid >> 2;
            float s = 0.f;
            #pragma unroll
            for (int w2 = 0; w2 < 16; w2++)
                s += red[(w2 * 4 + bb) * 17 + c];
            tot[bb * 16 + c] = s;
        } else if (tid < 68) {
            const int bb = tid - 64;
            float z = 0.f;
            #pragma unroll
            for (int w2 = 0; w2 < 16; w2++)
                z += red[(w2 * 4 + bb) * 17 + 16];
            zt[bb] = z;
        }
        __syncthreads();

        if (tid < BPC) {
            const int bb = tid;
            float inv = 1.f / zt[bb];
            float sv[16], n2 = 0.f;
            #pragma unroll
            for (int c = 0; c < 16; c++) {
                sv[c] = tot[bb * 16 + c] * inv;
                n2 += sv[c] * sv[c];
            }
            float nr = sqrtf(n2);
            float coef = (n2 / (1.f + n2)) / (nr + 1e-7f);
            #pragma unroll
            for (int c = 0; c < 16; c++) vsm[bb * 16 + c] = coef * sv[c];
        }
        __syncthreads();
    }

    // ---- Output (B, J, C) ----
    if (tid < 64) {
        const int bb = tid >> 4, c = tid & 15;
        out[((size_t)(bg * BPC + bb) * JCAPS + j) * CDIM + c] = vsm[bb * 16 + c];
    }
}

extern "C" void kernel_launch(void* const* d_in, const int* in_sizes, int n_in,
                              void* d_out, int out_size)
{
    const float* x = (const float*)d_in[0];
    const float* W = (const float*)d_in[1];
    if (n_in >= 2 &&
        in_sizes[0] == JCAPS * ICAPS * DDIM * CDIM &&
        in_sizes[1] == BATCH * ICAPS * DDIM) {
        const float* t = x; x = W; W = t;
    }
    float* out = (float*)d_out;

    cudaFuncSetAttribute(digitcaps_kernel,
                         cudaFuncAttributeMaxDynamicSharedMemorySize,
                         SMEMF * (int)sizeof(float));

    dim3 grid((BATCH / BPC) * JCAPS);   // 1280 CTAs
    digitcaps_kernel<<<grid, TPB, SMEMF * sizeof(float)>>>(x, W, out);
}